// round 7
// baseline (speedup 1.0000x reference)
#include <cuda_runtime.h>
#include <stdint.h>
#include <math.h>

#define BATCH 32
#define CHAN  256
#define HH    56
#define WW    56
#define S     (HH*WW)        // 3136
#define S4    (S/4)          // 784
#define QSPLIT 8
#define CQ    (CHAN/QSPLIT)  // 32
#define RNUM  1568           // removed_num = round(3136*0.5)
#define BPB   7              // blocks per batch in pool+mid kernel
#define NT    896            // threads per block (28 warps); 7*896 == 8*784

// scratch (no cudaMalloc allowed)
__device__ __align__(16) float g_part_max[QSPLIT*BATCH*S];
__device__ __align__(16) float g_part_sum[QSPLIT*BATCH*S];
__device__ __align__(16) float g_y[BATCH*S];
__device__ int g_cnt[BATCH];   // zero-init; reset by consumer each replay

// ---------------------------------------------------------------------------
// Kernel 1 (fused pool + middle): per batch, 7 blocks of 896 threads compute
// channel-partial max/sum (1 float4 spatial pos x 32 channels per thread,
// dual accumulator chains). The LAST block to finish a batch then runs the
// whole middle phase for that batch: combine -> conv+sigmoid -> exact radix
// select -> masked write to g_y. Mids overlap other batches' pool work.
// ---------------------------------------------------------------------------
__global__ void __launch_bounds__(NT) pool_mid(const float* __restrict__ x,
                                               const float* __restrict__ w) {
    __shared__ float pm[S];
    __shared__ float pa[S];
    __shared__ unsigned int uvals[S];
    __shared__ int hist[256];
    __shared__ float ws[18];
    __shared__ unsigned int s_prefix;
    __shared__ int s_r, s_less;
    __shared__ int tieIdx[256];
    __shared__ int tieCount;
    __shared__ int s_bound;
    __shared__ int amLast;

    const int b   = blockIdx.x / BPB;
    const int blk = blockIdx.x % BPB;
    const int t   = threadIdx.x;
    const int lane = t & 31;

    // ---- pool phase: one (q, s4) work item per thread ----
    {
        int idx = blk * NT + t;            // 0 .. 6271
        int q   = idx / S4;
        int s4  = idx % S4;

        const float4* p = reinterpret_cast<const float4*>(x)
                        + (size_t)(b * CHAN + q * CQ) * S4 + s4;

        float4 mx0 = make_float4(-INFINITY, -INFINITY, -INFINITY, -INFINITY);
        float4 mx1 = mx0;
        float4 sm0 = make_float4(0.f, 0.f, 0.f, 0.f);
        float4 sm1 = sm0;

        #pragma unroll 8
        for (int c = 0; c < CQ; c += 2) {
            float4 v0 = __ldcs(p + (size_t)c * S4);
            float4 v1 = __ldcs(p + (size_t)(c + 1) * S4);
            mx0.x = fmaxf(mx0.x, v0.x); mx0.y = fmaxf(mx0.y, v0.y);
            mx0.z = fmaxf(mx0.z, v0.z); mx0.w = fmaxf(mx0.w, v0.w);
            sm0.x += v0.x; sm0.y += v0.y; sm0.z += v0.z; sm0.w += v0.w;
            mx1.x = fmaxf(mx1.x, v1.x); mx1.y = fmaxf(mx1.y, v1.y);
            mx1.z = fmaxf(mx1.z, v1.z); mx1.w = fmaxf(mx1.w, v1.w);
            sm1.x += v1.x; sm1.y += v1.y; sm1.z += v1.z; sm1.w += v1.w;
        }
        float4 mx = make_float4(fmaxf(mx0.x, mx1.x), fmaxf(mx0.y, mx1.y),
                                fmaxf(mx0.z, mx1.z), fmaxf(mx0.w, mx1.w));
        float4 sm = make_float4(sm0.x + sm1.x, sm0.y + sm1.y,
                                sm0.z + sm1.z, sm0.w + sm1.w);

        int o = (q * BATCH + b) * S4 + s4;
        reinterpret_cast<float4*>(g_part_max)[o] = mx;
        reinterpret_cast<float4*>(g_part_sum)[o] = sm;
    }

    // ---- publish partials, elect the last block of this batch ----
    __threadfence();
    __syncthreads();
    if (t == 0) {
        int old = atomicAdd(&g_cnt[b], 1);
        amLast = (old == BPB - 1);
        if (amLast) g_cnt[b] = 0;          // replay-safe reset (sole owner now)
    }
    __syncthreads();
    if (!amLast) return;
    __threadfence();                        // acquire partials from peer blocks

    // ================= middle phase (this block only) =================
    if (t < 18) ws[t] = w[t];
    if (t < 256) hist[t] = 0;
    if (t == 0) { s_r = RNUM - 1; s_less = 0; s_prefix = 0u; tieCount = 0; }

    // combine QSPLIT partials -> pooled max/avg (float4 per thread)
    const float inv = 1.0f / (float)CHAN;
    if (t < S4) {
        float4 mx = make_float4(-INFINITY, -INFINITY, -INFINITY, -INFINITY);
        float4 sm = make_float4(0.f, 0.f, 0.f, 0.f);
        #pragma unroll
        for (int q = 0; q < QSPLIT; ++q) {
            int o = (q * BATCH + b) * S4 + t;
            float4 m = reinterpret_cast<const float4*>(g_part_max)[o];
            float4 s = reinterpret_cast<const float4*>(g_part_sum)[o];
            mx.x = fmaxf(mx.x, m.x); mx.y = fmaxf(mx.y, m.y);
            mx.z = fmaxf(mx.z, m.z); mx.w = fmaxf(mx.w, m.w);
            sm.x += s.x; sm.y += s.y; sm.z += s.z; sm.w += s.w;
        }
        sm.x *= inv; sm.y *= inv; sm.z *= inv; sm.w *= inv;
        reinterpret_cast<float4*>(pm)[t] = mx;
        reinterpret_cast<float4*>(pa)[t] = sm;
    }
    __syncthreads();

    // 3x3 conv (2ch->1ch, pad 1, cross-correlation OIHW) + sigmoid
    for (int i = t; i < S; i += NT) {
        int oh = i / WW, ow = i % WW;
        float acc = 0.f;
        #pragma unroll
        for (int ky = 0; ky < 3; ++ky) {
            int ih = oh + ky - 1;
            if (ih < 0 || ih >= HH) continue;
            #pragma unroll
            for (int kx = 0; kx < 3; ++kx) {
                int iw = ow + kx - 1;
                if (iw < 0 || iw >= WW) continue;
                int ii = ih * WW + iw;
                acc = fmaf(pm[ii], ws[ky * 3 + kx], acc);
                acc = fmaf(pa[ii], ws[9 + ky * 3 + kx], acc);
            }
        }
        uvals[i] = __float_as_uint(1.0f / (1.0f + expf(-acc)));
    }
    __syncthreads();

    // 4-pass radix select (8 bits/pass), warp-0 bin scan, 3 barriers/pass
    #pragma unroll
    for (int pass = 0; pass < 4; ++pass) {
        const int shift = 24 - 8 * pass;
        const unsigned int pmask = (pass == 0) ? 0u : (0xFFFFFFFFu << (32 - 8 * pass));
        const unsigned int pref  = s_prefix;

        for (int i = t; i < S; i += NT) {
            unsigned int u = uvals[i];
            if ((u & pmask) == pref)
                atomicAdd(&hist[(u >> shift) & 0xFF], 1);
        }
        __syncthreads();

        if (t < 32) {
            int base = t * 8;
            int h0 = hist[base + 0], h1 = hist[base + 1];
            int h2 = hist[base + 2], h3 = hist[base + 3];
            int h4 = hist[base + 4], h5 = hist[base + 5];
            int h6 = hist[base + 6], h7 = hist[base + 7];
            int tot = h0 + h1 + h2 + h3 + h4 + h5 + h6 + h7;

            int ex = tot;
            #pragma unroll
            for (int d = 1; d < 32; d <<= 1) {
                int n = __shfl_up_sync(0xFFFFFFFFu, ex, d);
                if (lane >= d) ex += n;
            }
            ex -= tot;

            int r = s_r;
            if (ex <= r && r < ex + tot) {
                int cum = ex, bin = base;
                int hh[8] = {h0,h1,h2,h3,h4,h5,h6,h7};
                #pragma unroll
                for (int k = 0; k < 8; ++k) {
                    if (cum + hh[k] > r) { bin = base + k; break; }
                    cum += hh[k];
                }
                s_r      = r - cum;
                s_less  += cum;
                s_prefix = pref | ((unsigned int)bin << shift);
            }
        }
        __syncthreads();

        if (pass < 3) {
            if (t < 256) hist[t] = 0;
            __syncthreads();
        }
    }

    const unsigned int T = s_prefix;
    const int zeroTies = RNUM - s_less;

    for (int i = t; i < S; i += NT) {
        if (uvals[i] == T) {
            int p = atomicAdd(&tieCount, 1);
            if (p < 256) tieIdx[p] = i;
        }
    }
    __syncthreads();

    if (t == 0) {
        int tc = tieCount < 256 ? tieCount : 256;
        for (int i = 1; i < tc; ++i) {        // expected tc == 1
            int v2 = tieIdx[i], j = i - 1;
            while (j >= 0 && tieIdx[j] > v2) { tieIdx[j + 1] = tieIdx[j]; --j; }
            tieIdx[j + 1] = v2;
        }
        int z = zeroTies < tc ? zeroTies : tc;
        s_bound = (z <= 0) ? 0 : (tieIdx[z - 1] + 1);
    }
    __syncthreads();

    const int bound = s_bound;
    float* yb = g_y + b * S;
    for (int i = t; i < S; i += NT) {
        unsigned int u = uvals[i];
        float v = __uint_as_float(u);
        if (u < T || (u == T && i < bound)) v = 0.0f;
        yb[i] = v;
    }
}

// ---------------------------------------------------------------------------
// Kernel 2: broadcast masked map to all 256 channels (write-roofline kernel).
// One float4 load (L2-hot) + one float4 store per thread.
// ---------------------------------------------------------------------------
__global__ void bcast(float* __restrict__ out) {
    int gid = blockIdx.x * blockDim.x + threadIdx.x;   // 0 .. BATCH*CHAN*S4-1
    int row = gid / S4;          // b*256 + c
    int s4  = gid % S4;
    int b   = row >> 8;
    float4 v = __ldg(reinterpret_cast<const float4*>(g_y) + b * S4 + s4);
    reinterpret_cast<float4*>(out)[gid] = v;
}

// ---------------------------------------------------------------------------
extern "C" void kernel_launch(void* const* d_in, const int* in_sizes, int n_in,
                              void* d_out, int out_size) {
    const float* x = (const float*)d_in[0];   // [32,256,56,56]
    const float* w = (const float*)d_in[1];   // [1,2,3,3]
    float* out = (float*)d_out;               // [32,256,56,56]

    pool_mid<<<BATCH * BPB, NT>>>(x, w);              // 224 blocks x 896 thr
    bcast<<<(BATCH * CHAN * S4) / 256, 256>>>(out);   // 25088 blocks
}

// round 8
// speedup vs baseline: 1.0748x; 1.0748x over previous
#include <cuda_runtime.h>
#include <stdint.h>
#include <math.h>

#define BATCH 32
#define CHAN  256
#define HH    56
#define WW    56
#define S     (HH*WW)        // 3136
#define S4    (S/4)          // 784
#define QSPLIT 8
#define CQ    (CHAN/QSPLIT)  // 32
#define RNUM  1568           // removed_num = round(3136*0.5)

// scratch (no cudaMalloc allowed)
__device__ __align__(16) float g_part_max[QSPLIT*BATCH*S];
__device__ __align__(16) float g_part_sum[QSPLIT*BATCH*S];
__device__ __align__(16) float g_y[BATCH*S];

// ---------------------------------------------------------------------------
// Kernel 1: partial channel max/sum. 784 blocks x 256 threads.
// Read-roofline kernel (~103 MB in, 6.4 MB partials out). At measured ceiling.
// ---------------------------------------------------------------------------
__global__ void pool_partial(const float* __restrict__ x) {
    int gid = blockIdx.x * blockDim.x + threadIdx.x;
    int q   = gid / (BATCH * S4);
    int rem = gid % (BATCH * S4);
    int b   = rem / S4;
    int s4  = rem % S4;

    const float4* p = reinterpret_cast<const float4*>(x)
                    + (size_t)(b * CHAN + q * CQ) * S4 + s4;

    float4 mx = make_float4(-INFINITY, -INFINITY, -INFINITY, -INFINITY);
    float4 sm = make_float4(0.f, 0.f, 0.f, 0.f);

    #pragma unroll 8
    for (int c = 0; c < CQ; ++c) {
        float4 v = __ldcs(p + (size_t)c * S4);   // read-once: stream past L2
        mx.x = fmaxf(mx.x, v.x); mx.y = fmaxf(mx.y, v.y);
        mx.z = fmaxf(mx.z, v.z); mx.w = fmaxf(mx.w, v.w);
        sm.x += v.x; sm.y += v.y; sm.z += v.z; sm.w += v.w;
    }

    int o = (q * BATCH + b) * S4 + s4;
    reinterpret_cast<float4*>(g_part_max)[o] = mx;
    reinterpret_cast<float4*>(g_part_sum)[o] = sm;
}

// ---------------------------------------------------------------------------
// Kernel 2 (fused middle): per batch -> combine partials, conv+sigmoid,
// barrier-lean exact radix select, masked write to g_y.
// One block per batch, 1024 threads.
// ---------------------------------------------------------------------------
__global__ void __launch_bounds__(1024, 1) fused_mid(const float* __restrict__ w) {
    __shared__ float pm[S];
    __shared__ float pa[S];
    __shared__ unsigned int uvals[S];     // sigmoid bits; >0 so uint order == float order
    __shared__ int hist[256];
    __shared__ float ws[18];
    __shared__ unsigned int s_prefix;
    __shared__ int s_r, s_less;
    __shared__ int tieIdx[256];
    __shared__ int tieCount;
    __shared__ int s_bound;

    const int b = blockIdx.x;
    const int t = threadIdx.x;
    const int lane = t & 31;

    if (t < 18) ws[t] = w[t];
    if (t < 256) hist[t] = 0;             // pre-clear for pass 0
    if (t == 0) { s_r = RNUM - 1; s_less = 0; s_prefix = 0u; tieCount = 0; }

    // --- combine QSPLIT partials -> pooled max/avg in smem (float4/thread) ---
    const float inv = 1.0f / (float)CHAN;
    if (t < S4) {
        float4 mx = make_float4(-INFINITY, -INFINITY, -INFINITY, -INFINITY);
        float4 sm = make_float4(0.f, 0.f, 0.f, 0.f);
        #pragma unroll
        for (int q = 0; q < QSPLIT; ++q) {
            int o = (q * BATCH + b) * S4 + t;
            float4 m = reinterpret_cast<const float4*>(g_part_max)[o];
            float4 s = reinterpret_cast<const float4*>(g_part_sum)[o];
            mx.x = fmaxf(mx.x, m.x); mx.y = fmaxf(mx.y, m.y);
            mx.z = fmaxf(mx.z, m.z); mx.w = fmaxf(mx.w, m.w);
            sm.x += s.x; sm.y += s.y; sm.z += s.z; sm.w += s.w;
        }
        sm.x *= inv; sm.y *= inv; sm.z *= inv; sm.w *= inv;
        reinterpret_cast<float4*>(pm)[t] = mx;
        reinterpret_cast<float4*>(pa)[t] = sm;
    }
    __syncthreads();

    // --- 3x3 conv (2ch->1ch, pad 1, cross-correlation OIHW) + sigmoid ---
    for (int i = t; i < S; i += 1024) {
        int oh = i / WW, ow = i % WW;
        float acc = 0.f;
        #pragma unroll
        for (int ky = 0; ky < 3; ++ky) {
            int ih = oh + ky - 1;
            if (ih < 0 || ih >= HH) continue;
            #pragma unroll
            for (int kx = 0; kx < 3; ++kx) {
                int iw = ow + kx - 1;
                if (iw < 0 || iw >= WW) continue;
                int ii = ih * WW + iw;
                acc = fmaf(pm[ii], ws[ky * 3 + kx], acc);
                acc = fmaf(pa[ii], ws[9 + ky * 3 + kx], acc);
            }
        }
        uvals[i] = __float_as_uint(1.0f / (1.0f + expf(-acc)));
    }
    __syncthreads();

    // --- 4-pass radix select, 3 barriers per pass, warp-0 bin scan ---
    #pragma unroll
    for (int pass = 0; pass < 4; ++pass) {
        const int shift = 24 - 8 * pass;
        const unsigned int pmask = (pass == 0) ? 0u : (0xFFFFFFFFu << (32 - 8 * pass));
        const unsigned int pref  = s_prefix;

        for (int i = t; i < S; i += 1024) {
            unsigned int u = uvals[i];
            if ((u & pmask) == pref)
                atomicAdd(&hist[(u >> shift) & 0xFF], 1);
        }
        __syncthreads();

        if (t < 32) {
            int base = t * 8;
            int h0 = hist[base + 0], h1 = hist[base + 1];
            int h2 = hist[base + 2], h3 = hist[base + 3];
            int h4 = hist[base + 4], h5 = hist[base + 5];
            int h6 = hist[base + 6], h7 = hist[base + 7];
            int tot = h0 + h1 + h2 + h3 + h4 + h5 + h6 + h7;

            int ex = tot;                         // -> exclusive prefix of lane totals
            #pragma unroll
            for (int d = 1; d < 32; d <<= 1) {
                int n = __shfl_up_sync(0xFFFFFFFFu, ex, d);
                if (lane >= d) ex += n;
            }
            ex -= tot;

            int r = s_r;
            if (ex <= r && r < ex + tot) {        // exactly one lane matches
                int cum = ex, bin = base;
                int hh[8] = {h0,h1,h2,h3,h4,h5,h6,h7};
                #pragma unroll
                for (int k = 0; k < 8; ++k) {
                    if (cum + hh[k] > r) { bin = base + k; break; }
                    cum += hh[k];
                }
                s_r      = r - cum;
                s_less  += cum;
                s_prefix = pref | ((unsigned int)bin << shift);
            }
        }
        __syncthreads();

        if (pass < 3) {                           // clear for next pass
            if (t < 256) hist[t] = 0;
            __syncthreads();
        }
    }

    const unsigned int T = s_prefix;
    const int zeroTies = RNUM - s_less;           // # ties (==T) to zero, ascending index

    for (int i = t; i < S; i += 1024) {
        if (uvals[i] == T) {
            int p = atomicAdd(&tieCount, 1);
            if (p < 256) tieIdx[p] = i;
        }
    }
    __syncthreads();

    if (t == 0) {
        int tc = tieCount < 256 ? tieCount : 256;
        for (int i = 1; i < tc; ++i) {            // expected tc == 1
            int v2 = tieIdx[i], j = i - 1;
            while (j >= 0 && tieIdx[j] > v2) { tieIdx[j + 1] = tieIdx[j]; --j; }
            tieIdx[j + 1] = v2;
        }
        int z = zeroTies < tc ? zeroTies : tc;
        s_bound = (z <= 0) ? 0 : (tieIdx[z - 1] + 1);
    }
    __syncthreads();

    const int bound = s_bound;
    float* yb = g_y + b * S;
    for (int i = t; i < S; i += 1024) {
        unsigned int u = uvals[i];
        float v = __uint_as_float(u);
        if (u < T || (u == T && i < bound)) v = 0.0f;
        yb[i] = v;
    }
}

// ---------------------------------------------------------------------------
// Kernel 3: broadcast masked map to all 256 channels.
// 1 float4 load -> 8 channel stores per thread; 3136 blocks (full chip).
// Cuts L2 load traffic 8x vs one-store-per-thread version.
// ---------------------------------------------------------------------------
__global__ void __launch_bounds__(256) bcast(float* __restrict__ out) {
    int gid  = blockIdx.x * 256 + threadIdx.x;    // 0 .. BATCH*32*S4-1
    int s4   = gid % S4;
    int rowg = gid / S4;                          // b*32 + cg
    int b    = rowg >> 5;
    int cg   = rowg & 31;

    float4 v = __ldg(reinterpret_cast<const float4*>(g_y) + b * S4 + s4);

    float4* p = reinterpret_cast<float4*>(out)
              + ((size_t)(b * CHAN + cg * 8)) * S4 + s4;
    #pragma unroll
    for (int k = 0; k < 8; ++k) {
        *p = v;
        p += S4;
    }
}

// ---------------------------------------------------------------------------
extern "C" void kernel_launch(void* const* d_in, const int* in_sizes, int n_in,
                              void* d_out, int out_size) {
    const float* x = (const float*)d_in[0];   // [32,256,56,56]
    const float* w = (const float*)d_in[1];   // [1,2,3,3]
    float* out = (float*)d_out;               // [32,256,56,56]

    pool_partial<<<(QSPLIT * BATCH * S4) / 256, 256>>>(x);   // 784 blocks
    fused_mid<<<BATCH, 1024>>>(w);                           // 32 blocks
    bcast<<<(BATCH * 32 * S4) / 256, 256>>>(out);            // 3136 blocks
}